// round 4
// baseline (speedup 1.0000x reference)
#include <cuda_runtime.h>
#include <mma.h>

using namespace nvcuda;

namespace {
constexpr int TB    = 256;   // threads per block (8 warps)
constexpr int MROWS = 32;    // batch rows per block
constexpr int HD    = 128;   // hidden
constexpr int DD    = 64;    // input dim
constexpr int TT    = 100;   // timesteps
constexpr int BB    = 4096;  // batch
constexpr int LD    = 132;   // padded ld for state tiles
constexpr int LDW   = 132;   // padded ld for W1T/W2T in smem
constexpr int LDX   = 68;    // padded ld for x tile

constexpr int SM_W      = 2 * 128 * LDW;
constexpr int SM_STATE  = 4 * MROWS * LD;     // h, tmp, kb, u
constexpr int SM_X      = MROWS * LDX;
constexpr int SM_BIAS   = 128 + 128 + 384 + 384 + 128 + 128;
constexpr int SM_FLOATS = SM_W + SM_STATE + SM_X + SM_BIAS + 8;
constexpr int SMEM_BYTES = SM_FLOATS * 4;     // ~216.6 KB (< 227KB opt-in)
}

__device__ __forceinline__ float tanh_fast(float x) {
    float e = __expf(2.0f * x);
    return 1.0f - 2.0f / (e + 1.0f);
}
__device__ __forceinline__ float sigm_fast(float x) {
    return 1.0f / (1.0f + __expf(-x));
}

// C[32x128] = A[32x128] @ Bsh ; Bsh k-major [128x128] in smem (pre-tf32).
// Plain tf32 — only used on the dt-damped ODE path.
__device__ __noinline__ void gemm_shB(const float* __restrict__ A, int lda,
                                      const float* __restrict__ Bsh,
                                      float* __restrict__ C, int warp)
{
    const int r0 = (warp & 1) * 16;
    const int c0 = (warp >> 1) * 32;
    wmma::fragment<wmma::accumulator, 16, 16, 8, float> acc0, acc1;
    wmma::fill_fragment(acc0, 0.0f);
    wmma::fill_fragment(acc1, 0.0f);
#pragma unroll 4
    for (int k0 = 0; k0 < 128; k0 += 8) {
        wmma::fragment<wmma::matrix_a, 16, 16, 8, wmma::precision::tf32, wmma::row_major> a;
        wmma::load_matrix_sync(a, A + r0 * lda + k0, lda);
#pragma unroll
        for (int i = 0; i < a.num_elements; i++) a.x[i] = wmma::__float_to_tf32(a.x[i]);
        wmma::fragment<wmma::matrix_b, 16, 16, 8, wmma::precision::tf32, wmma::row_major> b0, b1;
        wmma::load_matrix_sync(b0, Bsh + k0 * LDW + c0, LDW);
        wmma::load_matrix_sync(b1, Bsh + k0 * LDW + c0 + 16, LDW);
        wmma::mma_sync(acc0, a, b0, acc0);
        wmma::mma_sync(acc1, a, b1, acc1);
    }
    wmma::store_matrix_sync(C + r0 * LD + c0, acc0, LD, wmma::mem_row_major);
    wmma::store_matrix_sync(C + r0 * LD + c0 + 16, acc1, LD, wmma::mem_row_major);
}

// C[32x128] = A[32xK] @ Bg^T ; Bg is [>=128 x K] row-major in GLOBAL
// (pre-offset to the N-chunk). 3-term hi/lo tf32 split -> fp32-grade.
template <int K>
__device__ __noinline__ void gemm_glB_split(const float* __restrict__ A, int lda,
                                            const float* __restrict__ Bg,
                                            float* __restrict__ C, int warp)
{
    const int r0 = (warp & 1) * 16;
    const int c0 = (warp >> 1) * 32;
    wmma::fragment<wmma::accumulator, 16, 16, 8, float> acc0, acc1;
    wmma::fill_fragment(acc0, 0.0f);
    wmma::fill_fragment(acc1, 0.0f);
#pragma unroll 2
    for (int k0 = 0; k0 < K; k0 += 8) {
        wmma::fragment<wmma::matrix_a, 16, 16, 8, wmma::precision::tf32, wmma::row_major> ah, al;
        wmma::load_matrix_sync(ah, A + r0 * lda + k0, lda);
#pragma unroll
        for (int i = 0; i < ah.num_elements; i++) {
            float v  = ah.x[i];
            float vh = wmma::__float_to_tf32(v);
            ah.x[i] = vh;
            al.x[i] = wmma::__float_to_tf32(v - vh);
        }
        // col_major: element (k,n) at Bg[n*K + k]  -> B(k,n) = Wrow[n][k]
        wmma::fragment<wmma::matrix_b, 16, 16, 8, wmma::precision::tf32, wmma::col_major> bh0, bl0, bh1, bl1;
        wmma::load_matrix_sync(bh0, Bg + (size_t)(c0)      * K + k0, K);
        wmma::load_matrix_sync(bh1, Bg + (size_t)(c0 + 16) * K + k0, K);
#pragma unroll
        for (int i = 0; i < bh0.num_elements; i++) {
            float v0 = bh0.x[i], v1 = bh1.x[i];
            float h0 = wmma::__float_to_tf32(v0), h1 = wmma::__float_to_tf32(v1);
            bh0.x[i] = h0; bl0.x[i] = wmma::__float_to_tf32(v0 - h0);
            bh1.x[i] = h1; bl1.x[i] = wmma::__float_to_tf32(v1 - h1);
        }
        wmma::mma_sync(acc0, ah, bh0, acc0);
        wmma::mma_sync(acc1, ah, bh1, acc1);
        wmma::mma_sync(acc0, al, bh0, acc0);
        wmma::mma_sync(acc1, al, bh1, acc1);
        wmma::mma_sync(acc0, ah, bl0, acc0);
        wmma::mma_sync(acc1, ah, bl1, acc1);
    }
    wmma::store_matrix_sync(C + r0 * LD + c0, acc0, LD, wmma::mem_row_major);
    wmma::store_matrix_sync(C + r0 * LD + c0 + 16, acc1, LD, wmma::mem_row_major);
}

// sKb = tanh(X @ W1^T + b1) @ W2^T      (b2 added by the consumer)
__device__ __forceinline__ void f_raw(const float* X, float* sU, float* sKb,
                                      const float* sW1T, const float* sW2T,
                                      const float* sb1, int tid, int warp)
{
    gemm_shB(X, LD, sW1T, sU, warp);
    __syncthreads();
#pragma unroll
    for (int j = 0; j < 16; j++) {
        int idx = tid + j * TB;
        int m = idx >> 7, n = idx & 127;
        sU[m * LD + n] = tanh_fast(sU[m * LD + n] + sb1[n]);
    }
    __syncthreads();
    gemm_shB(sU, LD, sW2T, sKb, warp);
    __syncthreads();
}

__global__ void __launch_bounds__(TB, 1)
odernn_kernel(const float* __restrict__ x_seq, const float* __restrict__ t_seq,
              const float* __restrict__ W1,   const float* __restrict__ b1,
              const float* __restrict__ W2,   const float* __restrict__ b2,
              const float* __restrict__ W_ih, const float* __restrict__ W_hh,
              const float* __restrict__ b_ih, const float* __restrict__ b_hh,
              const float* __restrict__ W_mu, const float* __restrict__ b_mu,
              const float* __restrict__ W_lv, const float* __restrict__ b_lv,
              float* __restrict__ out)
{
    extern __shared__ float sm[];
    float* sW1T = sm;
    float* sW2T = sW1T + 128 * LDW;
    float* sH   = sW2T + 128 * LDW;
    float* sTmp = sH   + MROWS * LD;
    float* sKb  = sTmp + MROWS * LD;
    float* sU   = sKb  + MROWS * LD;
    float* sX   = sU   + MROWS * LD;
    float* sb1  = sX   + MROWS * LDX;
    float* sb2  = sb1  + 128;
    float* sbih = sb2  + 128;
    float* sbhh = sbih + 384;
    float* sbmu = sbhh + 384;
    float* sblv = sbmu + 128;
    float* sSub = sblv + 128;

    const int tid  = threadIdx.x;
    const int warp = tid >> 5;
    const int m0   = blockIdx.x * MROWS;

    // Stage W1/W2 transposed (k-major), pre-rounded to tf32; biases; h=0.
    for (int i = tid; i < 128 * 128; i += TB) {
        int n = i >> 7, k = i & 127;
        sW1T[k * LDW + n] = wmma::__float_to_tf32(W1[i]);
        sW2T[k * LDW + n] = wmma::__float_to_tf32(W2[i]);
    }
    for (int i = tid; i < 128; i += TB) {
        sb1[i] = b1[i]; sb2[i] = b2[i]; sbmu[i] = b_mu[i]; sblv[i] = b_lv[i];
    }
    for (int i = tid; i < 384; i += TB) { sbih[i] = b_ih[i]; sbhh[i] = b_hh[i]; }
    for (int i = tid; i < MROWS * LD; i += TB) sH[i] = 0.0f;
    __syncthreads();

    float racc[16];  // RK4 k-sum in registers

    for (int t = 0; t < TT; t++) {
        if (tid == 0) {
            float dt = (t == 0) ? 0.0f : (t_seq[t] - t_seq[t - 1]);  // t_seq[0,:]
            sSub[0] = dt * 0.25f;
        }
        for (int j = tid; j < MROWS * DD; j += TB) {
            int m = j >> 6, d = j & 63;
            sX[m * LDX + d] = x_seq[((size_t)(m0 + m) * TT + t) * DD + d];
        }
        __syncthreads();
        const float sub = sSub[0];

        if (t > 0) {
#pragma unroll 1
            for (int s = 0; s < 4; s++) {
                f_raw(sH, sU, sKb, sW1T, sW2T, sb1, tid, warp);           // k1
#pragma unroll
                for (int j = 0; j < 16; j++) {
                    int idx = tid + j * TB; int m = idx >> 7, n = idx & 127;
                    float k1 = sKb[m * LD + n] + sb2[n];
                    racc[j] = k1;
                    sTmp[m * LD + n] = sH[m * LD + n] + 0.5f * sub * k1;
                }
                __syncthreads();
                f_raw(sTmp, sU, sKb, sW1T, sW2T, sb1, tid, warp);         // k2
#pragma unroll
                for (int j = 0; j < 16; j++) {
                    int idx = tid + j * TB; int m = idx >> 7, n = idx & 127;
                    float k2 = sKb[m * LD + n] + sb2[n];
                    racc[j] += 2.0f * k2;
                    sTmp[m * LD + n] = sH[m * LD + n] + 0.5f * sub * k2;
                }
                __syncthreads();
                f_raw(sTmp, sU, sKb, sW1T, sW2T, sb1, tid, warp);         // k3
#pragma unroll
                for (int j = 0; j < 16; j++) {
                    int idx = tid + j * TB; int m = idx >> 7, n = idx & 127;
                    float k3 = sKb[m * LD + n] + sb2[n];
                    racc[j] += 2.0f * k3;
                    sTmp[m * LD + n] = sH[m * LD + n] + sub * k3;
                }
                __syncthreads();
                f_raw(sTmp, sU, sKb, sW1T, sW2T, sb1, tid, warp);         // k4
#pragma unroll
                for (int j = 0; j < 16; j++) {
                    int idx = tid + j * TB; int m = idx >> 7, n = idx & 127;
                    float k4 = sKb[m * LD + n] + sb2[n];
                    sH[m * LD + n] += (sub * (1.0f / 6.0f)) * (racc[j] + k4);
                }
                __syncthreads();
            }
        }

        // ---- GRU ---- chunk offsets within [3H]: r=0, z=128, n=256
        gemm_glB_split<64> (sX, LDX, W_ih + (size_t)0 * 64,    sU,  warp); // i_r
        gemm_glB_split<128>(sH, LD,  W_hh + (size_t)0 * 128,   sKb, warp); // h_r
        __syncthreads();
#pragma unroll
        for (int j = 0; j < 16; j++) {
            int idx = tid + j * TB; int m = idx >> 7, n = idx & 127;
            sTmp[m * LD + n] = sigm_fast(sU[m * LD + n] + sbih[n] +
                                         sKb[m * LD + n] + sbhh[n]);       // r
        }
        __syncthreads();
        gemm_glB_split<64> (sX, LDX, W_ih + (size_t)256 * 64,  sU,  warp); // i_n
        gemm_glB_split<128>(sH, LD,  W_hh + (size_t)256 * 128, sKb, warp); // h_n
        __syncthreads();
#pragma unroll
        for (int j = 0; j < 16; j++) {
            int idx = tid + j * TB; int m = idx >> 7, n = idx & 127;
            float nn = tanh_fast(sU[m * LD + n] + sbih[256 + n] +
                                 sTmp[m * LD + n] * (sKb[m * LD + n] + sbhh[256 + n]));
            sTmp[m * LD + n] = nn;   // overwrite r with n (same element)
        }
        __syncthreads();
        gemm_glB_split<64> (sX, LDX, W_ih + (size_t)128 * 64,  sU,  warp); // i_z
        gemm_glB_split<128>(sH, LD,  W_hh + (size_t)128 * 128, sKb, warp); // h_z
        __syncthreads();
#pragma unroll
        for (int j = 0; j < 16; j++) {
            int idx = tid + j * TB; int m = idx >> 7, n = idx & 127;
            float z = sigm_fast(sU[m * LD + n] + sbih[128 + n] +
                                sKb[m * LD + n] + sbhh[128 + n]);
            sH[m * LD + n] = (1.0f - z) * sTmp[m * LD + n] + z * sH[m * LD + n];
        }
        __syncthreads();
    }

    // ---- outputs: mu then logvar, each [B,H] row-major, concatenated ----
    gemm_glB_split<128>(sH, LD, W_mu, sU, warp);
    __syncthreads();
#pragma unroll
    for (int j = 0; j < 16; j++) {
        int idx = tid + j * TB; int m = idx >> 7, n = idx & 127;
        out[(size_t)(m0 + m) * HD + n] = sU[m * LD + n] + sbmu[n];
    }
    __syncthreads();
    gemm_glB_split<128>(sH, LD, W_lv, sU, warp);
    __syncthreads();
#pragma unroll
    for (int j = 0; j < 16; j++) {
        int idx = tid + j * TB; int m = idx >> 7, n = idx & 127;
        out[(size_t)BB * HD + (size_t)(m0 + m) * HD + n] = sU[m * LD + n] + sblv[n];
    }
}

extern "C" void kernel_launch(void* const* d_in, const int* in_sizes, int n_in,
                              void* d_out, int out_size)
{
    (void)in_sizes; (void)n_in; (void)out_size;
    static bool attr_done = false;
    if (!attr_done) {
        cudaFuncSetAttribute(odernn_kernel,
                             cudaFuncAttributeMaxDynamicSharedMemorySize, SMEM_BYTES);
        attr_done = true;
    }
    odernn_kernel<<<BB / MROWS, TB, SMEM_BYTES>>>(
        (const float*)d_in[0],  (const float*)d_in[1],
        (const float*)d_in[2],  (const float*)d_in[3],
        (const float*)d_in[4],  (const float*)d_in[5],
        (const float*)d_in[6],  (const float*)d_in[7],
        (const float*)d_in[8],  (const float*)d_in[9],
        (const float*)d_in[10], (const float*)d_in[11],
        (const float*)d_in[12], (const float*)d_in[13],
        (float*)d_out);
}

// round 5
// speedup vs baseline: 1.0377x; 1.0377x over previous
#include <cuda_runtime.h>
#include <mma.h>

using namespace nvcuda;

namespace {
constexpr int TB    = 512;   // threads per block (16 warps)
constexpr int MROWS = 32;    // batch rows per block
constexpr int HD    = 128;   // hidden
constexpr int DD    = 64;    // input dim
constexpr int TT    = 100;   // timesteps
constexpr int BB    = 4096;  // batch
constexpr int LD    = 132;   // padded ld for state tiles
constexpr int LDW   = 132;   // padded ld for W1T/W2T in smem
constexpr int LDX   = 68;    // padded ld for x tile

constexpr int SM_W      = 2 * 128 * LDW;
constexpr int SM_STATE  = 4 * MROWS * LD;     // h, tmp, kb, u
constexpr int SM_X      = MROWS * LDX;
constexpr int SM_BIAS   = 128 + 128 + 384 + 384 + 128 + 128;
constexpr int SM_FLOATS = SM_W + SM_STATE + SM_X + SM_BIAS + 8;
constexpr int SMEM_BYTES = SM_FLOATS * 4;     // ~216.6 KB (< 227KB opt-in)
}

__device__ __forceinline__ float tanh_fast(float x) {
    float e = __expf(2.0f * x);
    return 1.0f - 2.0f / (e + 1.0f);
}
__device__ __forceinline__ float sigm_fast(float x) {
    return 1.0f / (1.0f + __expf(-x));
}

// ---------------------------------------------------------------------------
// ODE-path GEMM: C[32x128] = A[32x128] @ Bsh, Bsh k-major [128x128] smem
// (pre-rounded tf32). 16 warps, each 16(M) x 16(N). Plain tf32 (dt-damped).
// ---------------------------------------------------------------------------
__device__ __forceinline__ void gemm_ode(const float* __restrict__ A, int lda,
                                         const float* __restrict__ Bsh,
                                         float* __restrict__ C, int warp)
{
    const int r0 = (warp & 1) * 16;
    const int c0 = (warp >> 1) * 16;
    wmma::fragment<wmma::accumulator, 16, 16, 8, float> acc;
    wmma::fill_fragment(acc, 0.0f);
#pragma unroll 4
    for (int k0 = 0; k0 < 128; k0 += 8) {
        wmma::fragment<wmma::matrix_a, 16, 16, 8, wmma::precision::tf32, wmma::row_major> a;
        wmma::load_matrix_sync(a, A + r0 * lda + k0, lda);
#pragma unroll
        for (int i = 0; i < a.num_elements; i++) a.x[i] = wmma::__float_to_tf32(a.x[i]);
        wmma::fragment<wmma::matrix_b, 16, 16, 8, wmma::precision::tf32, wmma::row_major> b;
        wmma::load_matrix_sync(b, Bsh + k0 * LDW + c0, LDW);
        wmma::mma_sync(acc, a, b, acc);
    }
    wmma::store_matrix_sync(C + r0 * LD + c0, acc, LD, wmma::mem_row_major);
}

// ---------------------------------------------------------------------------
// Split-precision accumulate: acc += A[r0:r0+16, 0:K] @ Bg^T[:, c0:c0+16]
// Bg is [>=c0+16 x K] row-major in GLOBAL. 3-term hi/lo tf32 split.
// ---------------------------------------------------------------------------
__device__ __forceinline__ void accum_seg_split16(
    wmma::fragment<wmma::accumulator, 16, 16, 8, float>& acc,
    const float* __restrict__ A, int lda,
    const float* __restrict__ Bg, int K, int r0, int c0)
{
#pragma unroll 2
    for (int k0 = 0; k0 < K; k0 += 8) {
        wmma::fragment<wmma::matrix_a, 16, 16, 8, wmma::precision::tf32, wmma::row_major> ah, al;
        wmma::load_matrix_sync(ah, A + r0 * lda + k0, lda);
#pragma unroll
        for (int i = 0; i < ah.num_elements; i++) {
            float v  = ah.x[i];
            float vh = wmma::__float_to_tf32(v);
            ah.x[i] = vh;
            al.x[i] = wmma::__float_to_tf32(v - vh);
        }
        wmma::fragment<wmma::matrix_b, 16, 16, 8, wmma::precision::tf32, wmma::col_major> bh, bl;
        wmma::load_matrix_sync(bh, Bg + (size_t)c0 * K + k0, K);
#pragma unroll
        for (int i = 0; i < bh.num_elements; i++) {
            float v = bh.x[i];
            float h = wmma::__float_to_tf32(v);
            bh.x[i] = h;
            bl.x[i] = wmma::__float_to_tf32(v - h);
        }
        wmma::mma_sync(acc, ah, bh, acc);
        wmma::mma_sync(acc, al, bh, acc);
        wmma::mma_sync(acc, ah, bl, acc);
    }
}

// Fused two-segment split GEMM (16 warps, 16x16 each):
// C[32x128] = A1[32xK1] @ B1^T + A2[32xK2] @ B2^T
__device__ __noinline__ void gemm_fused_split(
    const float* __restrict__ A1, int lda1, const float* __restrict__ B1, int K1,
    const float* __restrict__ A2, int lda2, const float* __restrict__ B2, int K2,
    float* __restrict__ C, int warp)
{
    const int r0 = (warp & 1) * 16;
    const int c0 = (warp >> 1) * 16;
    wmma::fragment<wmma::accumulator, 16, 16, 8, float> acc;
    wmma::fill_fragment(acc, 0.0f);
    accum_seg_split16(acc, A1, lda1, B1, K1, r0, c0);
    accum_seg_split16(acc, A2, lda2, B2, K2, r0, c0);
    wmma::store_matrix_sync(C + r0 * LD + c0, acc, LD, wmma::mem_row_major);
}

// 8-warp split GEMM (warps w8 = 0..7, each 16x32): C[32x128] = A[32xK] @ Bg^T
__device__ __noinline__ void gemm8_split(
    const float* __restrict__ A, int lda,
    const float* __restrict__ Bg, int K,
    float* __restrict__ C, int w8)
{
    const int r0 = (w8 & 1) * 16;
    const int c0 = (w8 >> 1) * 32;
    wmma::fragment<wmma::accumulator, 16, 16, 8, float> acc0, acc1;
    wmma::fill_fragment(acc0, 0.0f);
    wmma::fill_fragment(acc1, 0.0f);
    accum_seg_split16(acc0, A, lda, Bg, K, r0, c0);
    accum_seg_split16(acc1, A, lda, Bg, K, r0, c0 + 16);
    wmma::store_matrix_sync(C + r0 * LD + c0, acc0, LD, wmma::mem_row_major);
    wmma::store_matrix_sync(C + r0 * LD + c0 + 16, acc1, LD, wmma::mem_row_major);
}

// sKb = tanh(X @ W1^T + b1) @ W2^T      (b2 added by the consumer)
__device__ __noinline__ void f_raw(const float* X, float* sU, float* sKb,
                                   const float* sW1T, const float* sW2T,
                                   const float* sb1, int tid, int warp)
{
    gemm_ode(X, LD, sW1T, sU, warp);
    __syncthreads();
#pragma unroll
    for (int j = 0; j < 8; j++) {
        int idx = tid + j * TB;
        int m = idx >> 7, n = idx & 127;
        sU[m * LD + n] = tanh_fast(sU[m * LD + n] + sb1[n]);
    }
    __syncthreads();
    gemm_ode(sU, LD, sW2T, sKb, warp);
    __syncthreads();
}

__global__ void __launch_bounds__(TB, 1)
odernn_kernel(const float* __restrict__ x_seq, const float* __restrict__ t_seq,
              const float* __restrict__ W1,   const float* __restrict__ b1,
              const float* __restrict__ W2,   const float* __restrict__ b2,
              const float* __restrict__ W_ih, const float* __restrict__ W_hh,
              const float* __restrict__ b_ih, const float* __restrict__ b_hh,
              const float* __restrict__ W_mu, const float* __restrict__ b_mu,
              const float* __restrict__ W_lv, const float* __restrict__ b_lv,
              float* __restrict__ out)
{
    extern __shared__ float sm[];
    float* sW1T = sm;
    float* sW2T = sW1T + 128 * LDW;
    float* sH   = sW2T + 128 * LDW;
    float* sTmp = sH   + MROWS * LD;
    float* sKb  = sTmp + MROWS * LD;
    float* sU   = sKb  + MROWS * LD;
    float* sX   = sU   + MROWS * LD;
    float* sb1  = sX   + MROWS * LDX;
    float* sb2  = sb1  + 128;
    float* sbih = sb2  + 128;
    float* sbhh = sbih + 384;
    float* sbmu = sbhh + 384;
    float* sblv = sbmu + 128;
    float* sSub = sblv + 128;

    const int tid  = threadIdx.x;
    const int warp = tid >> 5;
    const int m0   = blockIdx.x * MROWS;

    // Stage W1/W2 transposed (k-major), pre-rounded to tf32; biases; h=0.
    for (int i = tid; i < 128 * 128; i += TB) {
        int n = i >> 7, k = i & 127;
        sW1T[k * LDW + n] = wmma::__float_to_tf32(W1[i]);
        sW2T[k * LDW + n] = wmma::__float_to_tf32(W2[i]);
    }
    for (int i = tid; i < 128; i += TB) {
        sb1[i] = b1[i]; sb2[i] = b2[i]; sbmu[i] = b_mu[i]; sblv[i] = b_lv[i];
    }
    if (tid < 384) { sbih[tid] = b_ih[tid]; sbhh[tid] = b_hh[tid]; }
    for (int i = tid; i < MROWS * LD; i += TB) sH[i] = 0.0f;
    __syncthreads();

    float racc[8];  // RK4 k-sum in registers (fixed idx<->element map)

    for (int t = 0; t < TT; t++) {
        if (tid == 0) {
            float dt = (t == 0) ? 0.0f : (t_seq[t] - t_seq[t - 1]);  // t_seq[0,:]
            sSub[0] = dt * 0.25f;
        }
        for (int j = tid; j < MROWS * DD; j += TB) {
            int m = j >> 6, d = j & 63;
            sX[m * LDX + d] = x_seq[((size_t)(m0 + m) * TT + t) * DD + d];
        }
        __syncthreads();
        const float sub = sSub[0];

        if (t > 0) {
#pragma unroll 1
            for (int s = 0; s < 4; s++) {
                f_raw(sH, sU, sKb, sW1T, sW2T, sb1, tid, warp);           // k1
#pragma unroll
                for (int j = 0; j < 8; j++) {
                    int idx = tid + j * TB; int m = idx >> 7, n = idx & 127;
                    float k1 = sKb[m * LD + n] + sb2[n];
                    racc[j] = k1;
                    sTmp[m * LD + n] = sH[m * LD + n] + 0.5f * sub * k1;
                }
                __syncthreads();
                f_raw(sTmp, sU, sKb, sW1T, sW2T, sb1, tid, warp);         // k2
#pragma unroll
                for (int j = 0; j < 8; j++) {
                    int idx = tid + j * TB; int m = idx >> 7, n = idx & 127;
                    float k2 = sKb[m * LD + n] + sb2[n];
                    racc[j] += 2.0f * k2;
                    sTmp[m * LD + n] = sH[m * LD + n] + 0.5f * sub * k2;
                }
                __syncthreads();
                f_raw(sTmp, sU, sKb, sW1T, sW2T, sb1, tid, warp);         // k3
#pragma unroll
                for (int j = 0; j < 8; j++) {
                    int idx = tid + j * TB; int m = idx >> 7, n = idx & 127;
                    float k3 = sKb[m * LD + n] + sb2[n];
                    racc[j] += 2.0f * k3;
                    sTmp[m * LD + n] = sH[m * LD + n] + sub * k3;
                }
                __syncthreads();
                f_raw(sTmp, sU, sKb, sW1T, sW2T, sb1, tid, warp);         // k4
#pragma unroll
                for (int j = 0; j < 8; j++) {
                    int idx = tid + j * TB; int m = idx >> 7, n = idx & 127;
                    float k4 = sKb[m * LD + n] + sb2[n];
                    sH[m * LD + n] += (sub * (1.0f / 6.0f)) * (racc[j] + k4);
                }
                __syncthreads();
            }
        }

        // ---- GRU ---- chunk offsets within [3H]: r=0, z=128, n=256
        // r gate: fused K=192 (gi_r + gh_r in one accumulator)
        gemm_fused_split(sX, LDX, W_ih + (size_t)0 * 64,  64,
                         sH, LD,  W_hh + (size_t)0 * 128, 128, sU, warp);
        __syncthreads();
#pragma unroll
        for (int j = 0; j < 8; j++) {
            int idx = tid + j * TB; int m = idx >> 7, n = idx & 127;
            sTmp[m * LD + n] = sigm_fast(sU[m * LD + n] + sbih[n] + sbhh[n]); // r
        }
        __syncthreads();
        // n gate: i_n (warps 0-7) and h_n (warps 8-15) concurrently
        if (warp < 8)
            gemm8_split(sX, LDX, W_ih + (size_t)256 * 64,  64,  sU,  warp);
        else
            gemm8_split(sH, LD,  W_hh + (size_t)256 * 128, 128, sKb, warp - 8);
        __syncthreads();
#pragma unroll
        for (int j = 0; j < 8; j++) {
            int idx = tid + j * TB; int m = idx >> 7, n = idx & 127;
            float nn = tanh_fast(sU[m * LD + n] + sbih[256 + n] +
                                 sTmp[m * LD + n] * (sKb[m * LD + n] + sbhh[256 + n]));
            sTmp[m * LD + n] = nn;   // overwrite r with n (same element)
        }
        __syncthreads();
        // z gate: fused K=192, then h update
        gemm_fused_split(sX, LDX, W_ih + (size_t)128 * 64,  64,
                         sH, LD,  W_hh + (size_t)128 * 128, 128, sU, warp);
        __syncthreads();
#pragma unroll
        for (int j = 0; j < 8; j++) {
            int idx = tid + j * TB; int m = idx >> 7, n = idx & 127;
            float z = sigm_fast(sU[m * LD + n] + sbih[128 + n] + sbhh[128 + n]);
            sH[m * LD + n] = (1.0f - z) * sTmp[m * LD + n] + z * sH[m * LD + n];
        }
        __syncthreads();
    }

    // ---- outputs: mu (warps 0-7) and logvar (warps 8-15) concurrently ----
    if (warp < 8)
        gemm8_split(sH, LD, W_mu, 128, sU,  warp);
    else
        gemm8_split(sH, LD, W_lv, 128, sKb, warp - 8);
    __syncthreads();
#pragma unroll
    for (int j = 0; j < 8; j++) {
        int idx = tid + j * TB; int m = idx >> 7, n = idx & 127;
        out[(size_t)(m0 + m) * HD + n] = sU[m * LD + n] + sbmu[n];
        out[(size_t)BB * HD + (size_t)(m0 + m) * HD + n] = sKb[m * LD + n] + sblv[n];
    }
}

extern "C" void kernel_launch(void* const* d_in, const int* in_sizes, int n_in,
                              void* d_out, int out_size)
{
    (void)in_sizes; (void)n_in; (void)out_size;
    static bool attr_done = false;
    if (!attr_done) {
        cudaFuncSetAttribute(odernn_kernel,
                             cudaFuncAttributeMaxDynamicSharedMemorySize, SMEM_BYTES);
        attr_done = true;
    }
    odernn_kernel<<<BB / MROWS, TB, SMEM_BYTES>>>(
        (const float*)d_in[0],  (const float*)d_in[1],
        (const float*)d_in[2],  (const float*)d_in[3],
        (const float*)d_in[4],  (const float*)d_in[5],
        (const float*)d_in[6],  (const float*)d_in[7],
        (const float*)d_in[8],  (const float*)d_in[9],
        (const float*)d_in[10], (const float*)d_in[11],
        (const float*)d_in[12], (const float*)d_in[13],
        (float*)d_out);
}